// round 13
// baseline (speedup 1.0000x reference)
#include <cuda_runtime.h>
#include <cuda_fp16.h>
#include <math.h>
#include <stdint.h>

#define N_EMBD   1024
#define N_HEAD   16
#define HEAD_DIM 64
#define BATCH    4
#define SEQ      2048
#define M_TOT    8192
#define QSCALE   (0.125f * 1.44269504088896340736f)   // 1/sqrt(64) * log2(e)

// ---------------------------------------------------------------------------
// Device scratch (fp16). Q,K,V all (B,H,T,D); O (B,T,C).
// Q pre-scaled by 1/8*log2(e) so softmax uses ex2 directly.
// ---------------------------------------------------------------------------
__device__ __half g_X[(size_t)M_TOT * N_EMBD];
__device__ __half g_Wt[4][(size_t)N_EMBD * N_EMBD];   // W^T [n][k]
__device__ __half g_Q[(size_t)BATCH * N_HEAD * SEQ * HEAD_DIM];
__device__ __half g_K[(size_t)BATCH * N_HEAD * SEQ * HEAD_DIM];
__device__ __half g_V[(size_t)BATCH * N_HEAD * SEQ * HEAD_DIM];
__device__ __half g_O[(size_t)M_TOT * N_EMBD];

// ---------------------------------------------------------------------------
__device__ __forceinline__ void mma_fp16(float* d, const unsigned* a,
                                         const unsigned* b) {
    asm volatile(
        "mma.sync.aligned.m16n8k16.row.col.f32.f16.f16.f32 "
        "{%0,%1,%2,%3}, {%4,%5,%6,%7}, {%8,%9}, {%0,%1,%2,%3};"
        : "+f"(d[0]), "+f"(d[1]), "+f"(d[2]), "+f"(d[3])
        : "r"(a[0]), "r"(a[1]), "r"(a[2]), "r"(a[3]), "r"(b[0]), "r"(b[1]));
}

__device__ __forceinline__ void ldm_x4(unsigned* r, uint32_t a) {
    asm volatile("ldmatrix.sync.aligned.m8n8.x4.shared.b16 {%0,%1,%2,%3}, [%4];"
                 : "=r"(r[0]), "=r"(r[1]), "=r"(r[2]), "=r"(r[3]) : "r"(a));
}
__device__ __forceinline__ void ldm_x4t(unsigned* r, uint32_t a) {
    asm volatile("ldmatrix.sync.aligned.m8n8.x4.trans.shared.b16 {%0,%1,%2,%3}, [%4];"
                 : "=r"(r[0]), "=r"(r[1]), "=r"(r[2]), "=r"(r[3]) : "r"(a));
}

__device__ __forceinline__ void cp16(void* smem_dst, const void* gsrc) {
    unsigned u = (unsigned)__cvta_generic_to_shared(smem_dst);
    asm volatile("cp.async.cg.shared.global [%0], [%1], 16;\n"
                 :: "r"(u), "l"(gsrc));
}
#define CP_COMMIT() asm volatile("cp.async.commit_group;\n" ::: "memory")
#define CP_WAIT(N)  asm volatile("cp.async.wait_group %0;\n" :: "n"(N) : "memory")

__device__ __forceinline__ uint32_t smem_u32(const void* p) {
    return (uint32_t)__cvta_generic_to_shared(p);
}
__device__ __forceinline__ unsigned h2u(__half2 h) { return *(unsigned*)&h; }

__device__ __forceinline__ float ex2(float x) {
    float r;
    asm("ex2.approx.f32 %0, %1;" : "=f"(r) : "f"(x));
    return r;
}

// ---------------------------------------------------------------------------
// prep kernels
// ---------------------------------------------------------------------------
__global__ void prep_x_kernel(const float* __restrict__ x) {
    size_t i = (size_t)blockIdx.x * 256 + threadIdx.x;
    float4 v = ((const float4*)x)[i];
    uint2 u;
    u.x = h2u(__floats2half2_rn(v.x, v.y));
    u.y = h2u(__floats2half2_rn(v.z, v.w));
    ((uint2*)g_X)[i] = u;
}

__global__ void prep_w_kernel(const float* __restrict__ Wq,
                              const float* __restrict__ Wk,
                              const float* __restrict__ Wv,
                              const float* __restrict__ Wp) {
    __shared__ float tile[32][33];
    int z = blockIdx.z;
    const float* W = (z == 0) ? Wq : (z == 1) ? Wk : (z == 2) ? Wv : Wp;
    int x0 = blockIdx.x * 32;
    int y0 = blockIdx.y * 32;
    int tx = threadIdx.x;
    for (int i = threadIdx.y; i < 32; i += 8)
        tile[i][tx] = W[(size_t)(y0 + i) * N_EMBD + x0 + tx];
    __syncthreads();
    for (int i = threadIdx.y; i < 32; i += 8)
        g_Wt[z][(size_t)(x0 + i) * N_EMBD + y0 + tx] = __float2half(tile[tx][i]);
}

// ---------------------------------------------------------------------------
// fp16 GEMM (ldmatrix): block 128x256, 512 threads = 16 warps (4x4),
// warp tile 32x64 (acc 64 regs -> ~110 regs/thread, 16 warps resident).
// BK=32, 2-stage cp.async double buffer (proven pattern). smem 61440 B.
// ---------------------------------------------------------------------------
#define GSTR 40
#define A_OFF(buf) ((buf) * 5120)
#define B_OFF(buf) (10240 + (buf) * 10240)
#define GEMM_SMEM_BYTES 61440
#define GTHREADS 512

__device__ __forceinline__ void gemm_load_stage(
    const __half* __restrict__ A, const __half* __restrict__ Bt,
    int m0, int n0, int kb, __half* smem, int buf, int tid)
{
    const int k0 = kb * 32;
    // A: 128 rows x 4 chunks = 512 cp16 (1 per thread)
    {
        int r = tid >> 2, ch = tid & 3;
        cp16(smem + A_OFF(buf) + r * GSTR + ch * 8,
             A + (size_t)(m0 + r) * N_EMBD + k0 + ch * 8);
    }
    // B: 256 rows x 4 chunks = 1024 cp16 (2 per thread)
#pragma unroll
    for (int i = 0; i < 2; i++) {
        int idx = tid + i * GTHREADS;
        int r = idx >> 2, ch = idx & 3;
        cp16(smem + B_OFF(buf) + r * GSTR + ch * 8,
             Bt + (size_t)(n0 + r) * N_EMBD + k0 + ch * 8);
    }
}

__device__ __forceinline__ void gemm_fp16_main(
    const __half* __restrict__ A, const __half* __restrict__ Bt,
    int m0, int n0, __half* smem, float acc[2][8][4])
{
    const int tid = threadIdx.x;
    const int warp = tid >> 5, lane = tid & 31;
    const int wm = (warp >> 2) * 32;       // warpM in {0..3}
    const int wn = (warp & 3) * 64;        // warpN in {0..3}
    const uint32_t sb = smem_u32(smem);
    const int a_lane = ((lane & 15) + wm) * GSTR + (lane >> 4) * 8;
    const int b_lane = ((lane >> 4) * 8 + (lane & 7) + wn) * GSTR +
                       ((lane >> 3) & 1) * 8;

#pragma unroll
    for (int mt = 0; mt < 2; mt++)
#pragma unroll
        for (int nt = 0; nt < 8; nt++)
#pragma unroll
            for (int j = 0; j < 4; j++) acc[mt][nt][j] = 0.f;

    gemm_load_stage(A, Bt, m0, n0, 0, smem, 0, tid);
    CP_COMMIT();

    for (int kb = 0; kb < 32; kb++) {
        __syncthreads();
        if (kb + 1 < 32) {
            gemm_load_stage(A, Bt, m0, n0, kb + 1, smem, (kb + 1) & 1, tid);
            CP_COMMIT();
            CP_WAIT(1);
        } else {
            CP_WAIT(0);
        }
        __syncthreads();

        const uint32_t Ab = sb + 2 * (A_OFF(kb & 1) + a_lane);
        const uint32_t Bb = sb + 2 * (B_OFF(kb & 1) + b_lane);
#pragma unroll
        for (int kk = 0; kk < 32; kk += 16) {
            unsigned af[2][4];
#pragma unroll
            for (int mt = 0; mt < 2; mt++)
                ldm_x4(af[mt], Ab + 2 * (mt * 16 * GSTR + kk));
            unsigned bf[8][2];
#pragma unroll
            for (int ntp = 0; ntp < 4; ntp++) {
                unsigned r[4];
                ldm_x4(r, Bb + 2 * (ntp * 16 * GSTR + kk));
                bf[2 * ntp][0] = r[0]; bf[2 * ntp][1] = r[1];
                bf[2 * ntp + 1][0] = r[2]; bf[2 * ntp + 1][1] = r[3];
            }
#pragma unroll
            for (int mt = 0; mt < 2; mt++)
#pragma unroll
                for (int nt = 0; nt < 8; nt++)
                    mma_fp16(acc[mt][nt], af[mt], bf[nt]);
        }
    }
}

// QKV: out (B,H,T,D) fp16, +bias; Q pre-scaled by 1/8*log2(e).
__global__ __launch_bounds__(GTHREADS, 1) void qkv_gemm_kernel(
    const float* __restrict__ bq, const float* __restrict__ bk,
    const float* __restrict__ bv)
{
    extern __shared__ __half smem[];
    const int z = blockIdx.z;
    const float* bias = (z == 0) ? bq : (z == 1) ? bk : bv;
    __half* out = (z == 0) ? g_Q : (z == 1) ? g_K : g_V;
    const float oscale = (z == 0) ? QSCALE : 1.0f;
    const int m0 = blockIdx.y * 128, n0 = blockIdx.x * 256;

    float acc[2][8][4];
    gemm_fp16_main(g_X, g_Wt[z], m0, n0, smem, acc);

    const int tid = threadIdx.x;
    const int warp = tid >> 5, lane = tid & 31;
    const int wm = (warp >> 2) * 32, wn = (warp & 3) * 64;
    const int gr = lane >> 2, gc = lane & 3;

#pragma unroll
    for (int mt = 0; mt < 2; mt++) {
#pragma unroll
        for (int nt = 0; nt < 8; nt++) {
            int n = n0 + wn + nt * 8 + 2 * gc;
            int h = n >> 6, d = n & 63;
            float2 bi = *(const float2*)&bias[n];
#pragma unroll
            for (int half_ = 0; half_ < 2; half_++) {
                int m = m0 + wm + mt * 16 + gr + half_ * 8;
                int bb = m >> 11, t = m & (SEQ - 1);
                float c0 = (acc[mt][nt][half_ * 2 + 0] + bi.x) * oscale;
                float c1 = (acc[mt][nt][half_ * 2 + 1] + bi.y) * oscale;
                *(__half2*)&out[(((size_t)(bb * N_HEAD + h)) * SEQ + t) * 64 + d] =
                    __floats2half2_rn(c0, c1);
            }
        }
    }
}

__global__ __launch_bounds__(GTHREADS, 1) void proj_gemm_kernel(
    const float* __restrict__ bp, float* __restrict__ out)
{
    extern __shared__ __half smem[];
    const int m0 = blockIdx.y * 128, n0 = blockIdx.x * 256;

    float acc[2][8][4];
    gemm_fp16_main(g_O, g_Wt[3], m0, n0, smem, acc);

    const int tid = threadIdx.x;
    const int warp = tid >> 5, lane = tid & 31;
    const int wm = (warp >> 2) * 32, wn = (warp & 3) * 64;
    const int gr = lane >> 2, gc = lane & 3;

#pragma unroll
    for (int mt = 0; mt < 2; mt++) {
#pragma unroll
        for (int nt = 0; nt < 8; nt++) {
            int n = n0 + wn + nt * 8 + 2 * gc;
            float2 bi = *(const float2*)&bp[n];
#pragma unroll
            for (int half_ = 0; half_ < 2; half_++) {
                int m = m0 + wm + mt * 16 + gr + half_ * 8;
                float2 v = make_float2(acc[mt][nt][half_ * 2 + 0] + bi.x,
                                       acc[mt][nt][half_ * 2 + 1] + bi.y);
                *(float2*)&out[(size_t)m * N_EMBD + n] = v;
            }
        }
    }
}

// ---------------------------------------------------------------------------
// Fused causal attention (UNCHANGED from R12, 148.0 us): fp16 mma, 64-key
// tiles, cp.async double-buffered, paired q-tiles, Q + P in registers,
// V natural layout via ldmatrix.trans, ex2 softmax in log2 domain.
// ---------------------------------------------------------------------------
#define QSH 72
#define KSH 72
#define VSH 72
#define QS_H (128 * QSH)
#define KS_H (64 * KSH)
#define VS_H (64 * VSH)
#define ATTN_SMEM_BYTES ((QS_H + 2 * KS_H + 2 * VS_H) * 2)  // 55296

__global__ __launch_bounds__(256, 2) void attn_kernel()
{
    extern __shared__ __half sm[];
    __half* Qs  = sm;
    __half* Ks0 = Qs + QS_H;
    __half* Vs0 = Ks0 + 2 * KS_H;
    const uint32_t sb = smem_u32(sm);

    const int px = blockIdx.x;          // 0..7
    const int h  = blockIdx.y;
    const int b  = blockIdx.z;
    const int tid  = threadIdx.x;
    const int warp = tid >> 5, lane = tid & 31;
    const int gr = lane >> 2, gc = lane & 3;
    const int rw = warp * 16;

    const __half* Kb = g_K + ((size_t)(b * N_HEAD + h)) * SEQ * 64;
    const __half* Vb = g_V + ((size_t)(b * N_HEAD + h)) * SEQ * 64;

    const int q_lane = (rw + (lane & 15)) * QSH + (lane >> 4) * 8;
    const int k_lane = ((lane >> 4) * 8 + (lane & 7)) * KSH + ((lane >> 3) & 1) * 8;
    const int v_lane = (lane & 15) * VSH + (lane >> 4) * 8;

    for (int pass = 0; pass < 2; pass++) {
        const int qt = pass ? px : (15 - px);
        const int q0 = qt * 128;
        const int nkt = 2 * qt + 2;     // 64-key tiles

        const __half* Qg = g_Q + (((size_t)(b * N_HEAD + h)) * SEQ + q0) * 64;

        // prologue: Q tile + KV tile 0 in one cp.async group
        {
#pragma unroll
            for (int i = 0; i < 4; i++) {
                int idx = tid + i * 256;
                int r = idx >> 3, ch = idx & 7;
                cp16(&Qs[r * QSH + ch * 8], Qg + r * 64 + ch * 8);
            }
#pragma unroll
            for (int i = 0; i < 2; i++) {
                int idx = tid + i * 256;
                int r = idx >> 3, ch = idx & 7;
                cp16(&Ks0[r * KSH + ch * 8], Kb + r * 64 + ch * 8);
                cp16(&Vs0[r * VSH + ch * 8], Vb + r * 64 + ch * 8);
            }
            CP_COMMIT();
        }

        float m_[2] = {-1e30f, -1e30f};
        float l_[2] = {0.f, 0.f};
        float o[8][4];
#pragma unroll
        for (int dt = 0; dt < 8; dt++)
#pragma unroll
            for (int j = 0; j < 4; j++) o[dt][j] = 0.f;

        unsigned qf[4][4];              // Q fragments, loaded once per pass
        const int row0 = q0 + rw + gr;
        const int row1 = row0 + 8;

        for (int kb = 0; kb < nkt; kb++) {
            __syncthreads();
            if (kb + 1 < nkt) {
                const __half* Kg = Kb + (size_t)(kb + 1) * 64 * 64;
                const __half* Vg = Vb + (size_t)(kb + 1) * 64 * 64;
                __half* Kd = Ks0 + ((kb + 1) & 1) * KS_H;
                __half* Vd = Vs0 + ((kb + 1) & 1) * VS_H;
#pragma unroll
                for (int i = 0; i < 2; i++) {
                    int idx = tid + i * 256;
                    int r = idx >> 3, ch = idx & 7;
                    cp16(&Kd[r * KSH + ch * 8], Kg + r * 64 + ch * 8);
                    cp16(&Vd[r * VSH + ch * 8], Vg + r * 64 + ch * 8);
                }
                CP_COMMIT();
                CP_WAIT(1);
            } else {
                CP_WAIT(0);
            }
            __syncthreads();

            if (kb == 0) {
                const uint32_t Qsb = sb + 2 * q_lane;
#pragma unroll
                for (int ch = 0; ch < 4; ch++)
                    ldm_x4(qf[ch], Qsb + 2 * (ch * 16));
            }

            if (kb * 64 > q0 + rw + 15) continue;   // fully masked for warp

            const uint32_t Ktb = sb + 2 * (QS_H + (kb & 1) * KS_H + k_lane);
            const uint32_t Vtb = sb + 2 * (QS_H + 2 * KS_H + (kb & 1) * VS_H + v_lane);

            // S = Q K^T (16 x 64) — S already in log2 domain (Q prescaled)
            float s[8][4];
#pragma unroll
            for (int nt = 0; nt < 8; nt++)
#pragma unroll
                for (int j = 0; j < 4; j++) s[nt][j] = 0.f;

#pragma unroll
            for (int ch = 0; ch < 4; ch++) {
                int k = ch * 16;
#pragma unroll
                for (int ntp = 0; ntp < 4; ntp++) {
                    unsigned r[4];
                    ldm_x4(r, Ktb + 2 * (ntp * 16 * KSH + k));
                    mma_fp16(s[2 * ntp], qf[ch], r);
                    mma_fp16(s[2 * ntp + 1], qf[ch], r + 2);
                }
            }

            // causal mask (only diagonal-straddling tiles)
            if (kb * 64 + 63 > q0 + rw) {
#pragma unroll
                for (int nt = 0; nt < 8; nt++) {
                    int c0 = kb * 64 + nt * 8 + 2 * gc;
                    if (c0     > row0) s[nt][0] = -1e30f;
                    if (c0 + 1 > row0) s[nt][1] = -1e30f;
                    if (c0     > row1) s[nt][2] = -1e30f;
                    if (c0 + 1 > row1) s[nt][3] = -1e30f;
                }
            }

            // online softmax in log2 domain: P = 2^(S - m)
            float mx0 = -1e30f, mx1 = -1e30f;
#pragma unroll
            for (int nt = 0; nt < 8; nt++) {
                mx0 = fmaxf(mx0, fmaxf(s[nt][0], s[nt][1]));
                mx1 = fmaxf(mx1, fmaxf(s[nt][2], s[nt][3]));
            }
#pragma unroll
            for (int off = 1; off < 4; off <<= 1) {
                mx0 = fmaxf(mx0, __shfl_xor_sync(0xffffffffu, mx0, off));
                mx1 = fmaxf(mx1, __shfl_xor_sync(0xffffffffu, mx1, off));
            }
            float mn0 = fmaxf(m_[0], mx0), mn1 = fmaxf(m_[1], mx1);
            float sc0 = ex2(m_[0] - mn0), sc1 = ex2(m_[1] - mn1);
            float sum0 = 0.f, sum1 = 0.f;
#pragma unroll
            for (int nt = 0; nt < 8; nt++) {
                s[nt][0] = ex2(s[nt][0] - mn0);
                s[nt][1] = ex2(s[nt][1] - mn0);
                s[nt][2] = ex2(s[nt][2] - mn1);
                s[nt][3] = ex2(s[nt][3] - mn1);
                sum0 += s[nt][0] + s[nt][1];
                sum1 += s[nt][2] + s[nt][3];
            }
#pragma unroll
            for (int off = 1; off < 4; off <<= 1) {
                sum0 += __shfl_xor_sync(0xffffffffu, sum0, off);
                sum1 += __shfl_xor_sync(0xffffffffu, sum1, off);
            }
            l_[0] = l_[0] * sc0 + sum0;
            l_[1] = l_[1] * sc1 + sum1;
            m_[0] = mn0;
            m_[1] = mn1;
#pragma unroll
            for (int dt = 0; dt < 8; dt++) {
                o[dt][0] *= sc0; o[dt][1] *= sc0;
                o[dt][2] *= sc1; o[dt][3] *= sc1;
            }

            // O += P @ V — P straight from S fragments (no smem round-trip)
#pragma unroll
            for (int ch = 0; ch < 4; ch++) {
                unsigned pa[4];
                pa[0] = h2u(__floats2half2_rn(s[2 * ch][0], s[2 * ch][1]));
                pa[1] = h2u(__floats2half2_rn(s[2 * ch][2], s[2 * ch][3]));
                pa[2] = h2u(__floats2half2_rn(s[2 * ch + 1][0], s[2 * ch + 1][1]));
                pa[3] = h2u(__floats2half2_rn(s[2 * ch + 1][2], s[2 * ch + 1][3]));
#pragma unroll
                for (int dtp = 0; dtp < 4; dtp++) {
                    unsigned r[4];
                    ldm_x4t(r, Vtb + 2 * (ch * 16 * VSH + dtp * 16));
                    mma_fp16(o[2 * dtp], pa, r);
                    mma_fp16(o[2 * dtp + 1], pa, r + 2);
                }
            }
        }

        // normalize + store fp16 to g_O (B,T,C)
        float inv0 = 1.f / l_[0];
        float inv1 = 1.f / l_[1];
#pragma unroll
        for (int dt = 0; dt < 8; dt++) {
            int col = h * 64 + dt * 8 + 2 * gc;
            *(__half2*)&g_O[((size_t)b * SEQ + row0) * N_EMBD + col] =
                __floats2half2_rn(o[dt][0] * inv0, o[dt][1] * inv0);
            *(__half2*)&g_O[((size_t)b * SEQ + row1) * N_EMBD + col] =
                __floats2half2_rn(o[dt][2] * inv1, o[dt][3] * inv1);
        }
        __syncthreads();   // smem reuse safety before next pass
    }
}

// ---------------------------------------------------------------------------
extern "C" void kernel_launch(void* const* d_in, const int* in_sizes, int n_in,
                              void* d_out, int out_size)
{
    const float* x  = (const float*)d_in[0];
    const float* Wq = (const float*)d_in[1];
    const float* bq = (const float*)d_in[2];
    const float* Wk = (const float*)d_in[3];
    const float* bk = (const float*)d_in[4];
    const float* Wv = (const float*)d_in[5];
    const float* bv = (const float*)d_in[6];
    const float* Wp = (const float*)d_in[7];
    const float* bp = (const float*)d_in[8];
    float* out = (float*)d_out;

    cudaFuncSetAttribute(qkv_gemm_kernel,
                         cudaFuncAttributeMaxDynamicSharedMemorySize,
                         GEMM_SMEM_BYTES);
    cudaFuncSetAttribute(proj_gemm_kernel,
                         cudaFuncAttributeMaxDynamicSharedMemorySize,
                         GEMM_SMEM_BYTES);
    cudaFuncSetAttribute(attn_kernel,
                         cudaFuncAttributeMaxDynamicSharedMemorySize,
                         ATTN_SMEM_BYTES);

    prep_x_kernel<<<M_TOT * N_EMBD / 4 / 256, 256>>>(x);
    prep_w_kernel<<<dim3(32, 32, 4), dim3(32, 8)>>>(Wq, Wk, Wv, Wp);

    qkv_gemm_kernel<<<dim3(4, 64, 3), GTHREADS, GEMM_SMEM_BYTES>>>(bq, bk, bv);

    attn_kernel<<<dim3(8, N_HEAD, BATCH), 256, ATTN_SMEM_BYTES>>>();

    proj_gemm_kernel<<<dim3(4, 64, 1), GTHREADS, GEMM_SMEM_BYTES>>>(bp, out);
}

// round 14
// speedup vs baseline: 1.0357x; 1.0357x over previous
#include <cuda_runtime.h>
#include <cuda_fp16.h>
#include <math.h>
#include <stdint.h>

#define N_EMBD   1024
#define N_HEAD   16
#define HEAD_DIM 64
#define BATCH    4
#define SEQ      2048
#define M_TOT    8192
#define QSCALE   (0.125f * 1.44269504088896340736f)   // 1/sqrt(64) * log2(e)

// ---------------------------------------------------------------------------
// Device scratch (fp16). Q,K,V all (B,H,T,D); O (B,T,C).
// Q pre-scaled by 1/8*log2(e) so softmax uses ex2 directly.
// ---------------------------------------------------------------------------
__device__ __half g_X[(size_t)M_TOT * N_EMBD];
__device__ __half g_Wt[4][(size_t)N_EMBD * N_EMBD];   // W^T [n][k]
__device__ __half g_Q[(size_t)BATCH * N_HEAD * SEQ * HEAD_DIM];
__device__ __half g_K[(size_t)BATCH * N_HEAD * SEQ * HEAD_DIM];
__device__ __half g_V[(size_t)BATCH * N_HEAD * SEQ * HEAD_DIM];
__device__ __half g_O[(size_t)M_TOT * N_EMBD];

// ---------------------------------------------------------------------------
__device__ __forceinline__ void mma_fp16(float* d, const unsigned* a,
                                         const unsigned* b) {
    asm volatile(
        "mma.sync.aligned.m16n8k16.row.col.f32.f16.f16.f32 "
        "{%0,%1,%2,%3}, {%4,%5,%6,%7}, {%8,%9}, {%0,%1,%2,%3};"
        : "+f"(d[0]), "+f"(d[1]), "+f"(d[2]), "+f"(d[3])
        : "r"(a[0]), "r"(a[1]), "r"(a[2]), "r"(a[3]), "r"(b[0]), "r"(b[1]));
}

__device__ __forceinline__ void ldm_x4(unsigned* r, uint32_t a) {
    asm volatile("ldmatrix.sync.aligned.m8n8.x4.shared.b16 {%0,%1,%2,%3}, [%4];"
                 : "=r"(r[0]), "=r"(r[1]), "=r"(r[2]), "=r"(r[3]) : "r"(a));
}
__device__ __forceinline__ void ldm_x4t(unsigned* r, uint32_t a) {
    asm volatile("ldmatrix.sync.aligned.m8n8.x4.trans.shared.b16 {%0,%1,%2,%3}, [%4];"
                 : "=r"(r[0]), "=r"(r[1]), "=r"(r[2]), "=r"(r[3]) : "r"(a));
}

__device__ __forceinline__ void cp16(void* smem_dst, const void* gsrc) {
    unsigned u = (unsigned)__cvta_generic_to_shared(smem_dst);
    asm volatile("cp.async.cg.shared.global [%0], [%1], 16;\n"
                 :: "r"(u), "l"(gsrc));
}
// L1-caching variant for high-reuse weight/activation streams in the GEMMs.
__device__ __forceinline__ void cp16ca(void* smem_dst, const void* gsrc) {
    unsigned u = (unsigned)__cvta_generic_to_shared(smem_dst);
    asm volatile("cp.async.ca.shared.global [%0], [%1], 16;\n"
                 :: "r"(u), "l"(gsrc));
}
#define CP_COMMIT() asm volatile("cp.async.commit_group;\n" ::: "memory")
#define CP_WAIT(N)  asm volatile("cp.async.wait_group %0;\n" :: "n"(N) : "memory")

__device__ __forceinline__ uint32_t smem_u32(const void* p) {
    return (uint32_t)__cvta_generic_to_shared(p);
}
__device__ __forceinline__ unsigned h2u(__half2 h) { return *(unsigned*)&h; }

__device__ __forceinline__ float ex2(float x) {
    float r;
    asm("ex2.approx.f32 %0, %1;" : "=f"(r) : "f"(x));
    return r;
}

// ---------------------------------------------------------------------------
// prep: fused x-cast + W-transpose. z=0..3 -> W q/k/v/p; z=4..11 -> x slabs.
// ---------------------------------------------------------------------------
__global__ void prep_kernel(const float* __restrict__ x,
                            const float* __restrict__ Wq,
                            const float* __restrict__ Wk,
                            const float* __restrict__ Wv,
                            const float* __restrict__ Wp) {
    int z = blockIdx.z;
    if (z >= 4) {
        // x cast: 8 z-slabs x 1024 blocks of (32x8) threads, 4 floats each
        size_t i = ((size_t)(z - 4) * 1024 + blockIdx.y * 32 + blockIdx.x) * 256 +
                   threadIdx.y * 32 + threadIdx.x;
        if (i < (size_t)M_TOT * N_EMBD / 4) {
            float4 v = ((const float4*)x)[i];
            uint2 u;
            u.x = h2u(__floats2half2_rn(v.x, v.y));
            u.y = h2u(__floats2half2_rn(v.z, v.w));
            ((uint2*)g_X)[i] = u;
        }
        return;
    }
    __shared__ float tile[32][33];
    const float* W = (z == 0) ? Wq : (z == 1) ? Wk : (z == 2) ? Wv : Wp;
    int x0 = blockIdx.x * 32;
    int y0 = blockIdx.y * 32;
    int tx = threadIdx.x;
    for (int i = threadIdx.y; i < 32; i += 8)
        tile[i][tx] = W[(size_t)(y0 + i) * N_EMBD + x0 + tx];
    __syncthreads();
    for (int i = threadIdx.y; i < 32; i += 8)
        g_Wt[z][(size_t)(x0 + i) * N_EMBD + y0 + tx] = __float2half(tile[tx][i]);
}

// ---------------------------------------------------------------------------
// fp16 GEMM (ldmatrix): block 128x256, 8 warps (2x4) of 64x64, BK=32,
// 2-stage cp.async double buffer (R9/R12-proven). .ca loads (L1 reuse).
// Stride 40 halves. smem 61440 bytes -> 2 CTAs/SM.
// ---------------------------------------------------------------------------
#define GSTR 40
#define A_OFF(buf) ((buf) * 5120)
#define B_OFF(buf) (10240 + (buf) * 10240)
#define GEMM_SMEM_BYTES 61440

__device__ __forceinline__ void gemm_load_stage(
    const __half* __restrict__ A, const __half* __restrict__ Bt,
    int m0, int n0, int kb, __half* smem, int buf, int tid)
{
    const int k0 = kb * 32;
#pragma unroll
    for (int i = 0; i < 2; i++) {
        int idx = tid + i * 256;
        int r = idx >> 2, ch = idx & 3;
        cp16ca(smem + A_OFF(buf) + r * GSTR + ch * 8,
               A + (size_t)(m0 + r) * N_EMBD + k0 + ch * 8);
    }
#pragma unroll
    for (int i = 0; i < 4; i++) {
        int idx = tid + i * 256;
        int r = idx >> 2, ch = idx & 3;
        cp16ca(smem + B_OFF(buf) + r * GSTR + ch * 8,
               Bt + (size_t)(n0 + r) * N_EMBD + k0 + ch * 8);
    }
}

__device__ __forceinline__ void gemm_fp16_main(
    const __half* __restrict__ A, const __half* __restrict__ Bt,
    int m0, int n0, __half* smem, float acc[4][8][4])
{
    const int tid = threadIdx.x;
    const int warp = tid >> 5, lane = tid & 31;
    const int wm = (warp >> 2) * 64;
    const int wn = (warp & 3) * 64;
    const uint32_t sb = smem_u32(smem);
    const int a_lane = ((lane & 15) + wm) * GSTR + (lane >> 4) * 8;
    const int b_lane = ((lane >> 4) * 8 + (lane & 7) + wn) * GSTR +
                       ((lane >> 3) & 1) * 8;

#pragma unroll
    for (int mt = 0; mt < 4; mt++)
#pragma unroll
        for (int nt = 0; nt < 8; nt++)
#pragma unroll
            for (int j = 0; j < 4; j++) acc[mt][nt][j] = 0.f;

    gemm_load_stage(A, Bt, m0, n0, 0, smem, 0, tid);
    CP_COMMIT();

    for (int kb = 0; kb < 32; kb++) {
        __syncthreads();
        if (kb + 1 < 32) {
            gemm_load_stage(A, Bt, m0, n0, kb + 1, smem, (kb + 1) & 1, tid);
            CP_COMMIT();
            CP_WAIT(1);
        } else {
            CP_WAIT(0);
        }
        __syncthreads();

        const uint32_t Ab = sb + 2 * (A_OFF(kb & 1) + a_lane);
        const uint32_t Bb = sb + 2 * (B_OFF(kb & 1) + b_lane);
#pragma unroll
        for (int kk = 0; kk < 32; kk += 16) {
            unsigned af[4][4];
#pragma unroll
            for (int mt = 0; mt < 4; mt++)
                ldm_x4(af[mt], Ab + 2 * (mt * 16 * GSTR + kk));
            unsigned bf[8][2];
#pragma unroll
            for (int ntp = 0; ntp < 4; ntp++) {
                unsigned r[4];
                ldm_x4(r, Bb + 2 * (ntp * 16 * GSTR + kk));
                bf[2 * ntp][0] = r[0]; bf[2 * ntp][1] = r[1];
                bf[2 * ntp + 1][0] = r[2]; bf[2 * ntp + 1][1] = r[3];
            }
#pragma unroll
            for (int mt = 0; mt < 4; mt++)
#pragma unroll
                for (int nt = 0; nt < 8; nt++)
                    mma_fp16(acc[mt][nt], af[mt], bf[nt]);
        }
    }
}

// QKV: out (B,H,T,D) fp16, +bias; Q pre-scaled by 1/8*log2(e).
__global__ __launch_bounds__(256, 1) void qkv_gemm_kernel(
    const float* __restrict__ bq, const float* __restrict__ bk,
    const float* __restrict__ bv)
{
    extern __shared__ __half smem[];
    const int z = blockIdx.z;
    const float* bias = (z == 0) ? bq : (z == 1) ? bk : bv;
    __half* out = (z == 0) ? g_Q : (z == 1) ? g_K : g_V;
    const float oscale = (z == 0) ? QSCALE : 1.0f;
    const int m0 = blockIdx.y * 128, n0 = blockIdx.x * 256;

    float acc[4][8][4];
    gemm_fp16_main(g_X, g_Wt[z], m0, n0, smem, acc);

    const int tid = threadIdx.x;
    const int warp = tid >> 5, lane = tid & 31;
    const int wm = (warp >> 2) * 64, wn = (warp & 3) * 64;
    const int gr = lane >> 2, gc = lane & 3;

#pragma unroll
    for (int mt = 0; mt < 4; mt++) {
#pragma unroll
        for (int nt = 0; nt < 8; nt++) {
            int n = n0 + wn + nt * 8 + 2 * gc;
            int h = n >> 6, d = n & 63;
            float2 bi = *(const float2*)&bias[n];
#pragma unroll
            for (int half_ = 0; half_ < 2; half_++) {
                int m = m0 + wm + mt * 16 + gr + half_ * 8;
                int bb = m >> 11, t = m & (SEQ - 1);
                float c0 = (acc[mt][nt][half_ * 2 + 0] + bi.x) * oscale;
                float c1 = (acc[mt][nt][half_ * 2 + 1] + bi.y) * oscale;
                *(__half2*)&out[(((size_t)(bb * N_HEAD + h)) * SEQ + t) * 64 + d] =
                    __floats2half2_rn(c0, c1);
            }
        }
    }
}

__global__ __launch_bounds__(256, 1) void proj_gemm_kernel(
    const float* __restrict__ bp, float* __restrict__ out)
{
    extern __shared__ __half smem[];
    const int m0 = blockIdx.y * 128, n0 = blockIdx.x * 256;

    float acc[4][8][4];
    gemm_fp16_main(g_O, g_Wt[3], m0, n0, smem, acc);

    const int tid = threadIdx.x;
    const int warp = tid >> 5, lane = tid & 31;
    const int wm = (warp >> 2) * 64, wn = (warp & 3) * 64;
    const int gr = lane >> 2, gc = lane & 3;

#pragma unroll
    for (int mt = 0; mt < 4; mt++) {
#pragma unroll
        for (int nt = 0; nt < 8; nt++) {
            int n = n0 + wn + nt * 8 + 2 * gc;
            float2 bi = *(const float2*)&bp[n];
#pragma unroll
            for (int half_ = 0; half_ < 2; half_++) {
                int m = m0 + wm + mt * 16 + gr + half_ * 8;
                float2 v = make_float2(acc[mt][nt][half_ * 2 + 0] + bi.x,
                                       acc[mt][nt][half_ * 2 + 1] + bi.y);
                *(float2*)&out[(size_t)m * N_EMBD + n] = v;
            }
        }
    }
}

// ---------------------------------------------------------------------------
// Fused causal attention (UNCHANGED, 147.4 us): fp16 mma, 64-key tiles,
// cp.async double-buffered, paired q-tiles, Q + P in registers, V natural
// layout via ldmatrix.trans, ex2 softmax in log2 domain.
// ---------------------------------------------------------------------------
#define QSH 72
#define KSH 72
#define VSH 72
#define QS_H (128 * QSH)
#define KS_H (64 * KSH)
#define VS_H (64 * VSH)
#define ATTN_SMEM_BYTES ((QS_H + 2 * KS_H + 2 * VS_H) * 2)  // 55296

__global__ __launch_bounds__(256, 2) void attn_kernel()
{
    extern __shared__ __half sm[];
    __half* Qs  = sm;
    __half* Ks0 = Qs + QS_H;
    __half* Vs0 = Ks0 + 2 * KS_H;
    const uint32_t sb = smem_u32(sm);

    const int px = blockIdx.x;          // 0..7
    const int h  = blockIdx.y;
    const int b  = blockIdx.z;
    const int tid  = threadIdx.x;
    const int warp = tid >> 5, lane = tid & 31;
    const int gr = lane >> 2, gc = lane & 3;
    const int rw = warp * 16;

    const __half* Kb = g_K + ((size_t)(b * N_HEAD + h)) * SEQ * 64;
    const __half* Vb = g_V + ((size_t)(b * N_HEAD + h)) * SEQ * 64;

    const int q_lane = (rw + (lane & 15)) * QSH + (lane >> 4) * 8;
    const int k_lane = ((lane >> 4) * 8 + (lane & 7)) * KSH + ((lane >> 3) & 1) * 8;
    const int v_lane = (lane & 15) * VSH + (lane >> 4) * 8;

    for (int pass = 0; pass < 2; pass++) {
        const int qt = pass ? px : (15 - px);
        const int q0 = qt * 128;
        const int nkt = 2 * qt + 2;     // 64-key tiles

        const __half* Qg = g_Q + (((size_t)(b * N_HEAD + h)) * SEQ + q0) * 64;

        // prologue: Q tile + KV tile 0 in one cp.async group
        {
#pragma unroll
            for (int i = 0; i < 4; i++) {
                int idx = tid + i * 256;
                int r = idx >> 3, ch = idx & 7;
                cp16(&Qs[r * QSH + ch * 8], Qg + r * 64 + ch * 8);
            }
#pragma unroll
            for (int i = 0; i < 2; i++) {
                int idx = tid + i * 256;
                int r = idx >> 3, ch = idx & 7;
                cp16(&Ks0[r * KSH + ch * 8], Kb + r * 64 + ch * 8);
                cp16(&Vs0[r * VSH + ch * 8], Vb + r * 64 + ch * 8);
            }
            CP_COMMIT();
        }

        float m_[2] = {-1e30f, -1e30f};
        float l_[2] = {0.f, 0.f};
        float o[8][4];
#pragma unroll
        for (int dt = 0; dt < 8; dt++)
#pragma unroll
            for (int j = 0; j < 4; j++) o[dt][j] = 0.f;

        unsigned qf[4][4];              // Q fragments, loaded once per pass
        const int row0 = q0 + rw + gr;
        const int row1 = row0 + 8;

        for (int kb = 0; kb < nkt; kb++) {
            __syncthreads();
            if (kb + 1 < nkt) {
                const __half* Kg = Kb + (size_t)(kb + 1) * 64 * 64;
                const __half* Vg = Vb + (size_t)(kb + 1) * 64 * 64;
                __half* Kd = Ks0 + ((kb + 1) & 1) * KS_H;
                __half* Vd = Vs0 + ((kb + 1) & 1) * VS_H;
#pragma unroll
                for (int i = 0; i < 2; i++) {
                    int idx = tid + i * 256;
                    int r = idx >> 3, ch = idx & 7;
                    cp16(&Kd[r * KSH + ch * 8], Kg + r * 64 + ch * 8);
                    cp16(&Vd[r * VSH + ch * 8], Vg + r * 64 + ch * 8);
                }
                CP_COMMIT();
                CP_WAIT(1);
            } else {
                CP_WAIT(0);
            }
            __syncthreads();

            if (kb == 0) {
                const uint32_t Qsb = sb + 2 * q_lane;
#pragma unroll
                for (int ch = 0; ch < 4; ch++)
                    ldm_x4(qf[ch], Qsb + 2 * (ch * 16));
            }

            if (kb * 64 > q0 + rw + 15) continue;   // fully masked for warp

            const uint32_t Ktb = sb + 2 * (QS_H + (kb & 1) * KS_H + k_lane);
            const uint32_t Vtb = sb + 2 * (QS_H + 2 * KS_H + (kb & 1) * VS_H + v_lane);

            // S = Q K^T (16 x 64) — S already in log2 domain (Q prescaled)
            float s[8][4];
#pragma unroll
            for (int nt = 0; nt < 8; nt++)
#pragma unroll
                for (int j = 0; j < 4; j++) s[nt][j] = 0.f;

#pragma unroll
            for (int ch = 0; ch < 4; ch++) {
                int k = ch * 16;
#pragma unroll
                for (int ntp = 0; ntp < 4; ntp++) {
                    unsigned r[4];
                    ldm_x4(r, Ktb + 2 * (ntp * 16 * KSH + k));
                    mma_fp16(s[2 * ntp], qf[ch], r);
                    mma_fp16(s[2 * ntp + 1], qf[ch], r + 2);
                }
            }

            // causal mask (only diagonal-straddling tiles)
            if (kb * 64 + 63 > q0 + rw) {
#pragma unroll
                for (int nt = 0; nt < 8; nt++) {
                    int c0 = kb * 64 + nt * 8 + 2 * gc;
                    if (c0     > row0) s[nt][0] = -1e30f;
                    if (c0 + 1 > row0) s[nt][1] = -1e30f;
                    if (c0     > row1) s[nt][2] = -1e30f;
                    if (c0 + 1 > row1) s[nt][3] = -1e30f;
                }
            }

            // online softmax in log2 domain: P = 2^(S - m)
            float mx0 = -1e30f, mx1 = -1e30f;
#pragma unroll
            for (int nt = 0; nt < 8; nt++) {
                mx0 = fmaxf(mx0, fmaxf(s[nt][0], s[nt][1]));
                mx1 = fmaxf(mx1, fmaxf(s[nt][2], s[nt][3]));
            }
#pragma unroll
            for (int off = 1; off < 4; off <<= 1) {
                mx0 = fmaxf(mx0, __shfl_xor_sync(0xffffffffu, mx0, off));
                mx1 = fmaxf(mx1, __shfl_xor_sync(0xffffffffu, mx1, off));
            }
            float mn0 = fmaxf(m_[0], mx0), mn1 = fmaxf(m_[1], mx1);
            float sc0 = ex2(m_[0] - mn0), sc1 = ex2(m_[1] - mn1);
            float sum0 = 0.f, sum1 = 0.f;
#pragma unroll
            for (int nt = 0; nt < 8; nt++) {
                s[nt][0] = ex2(s[nt][0] - mn0);
                s[nt][1] = ex2(s[nt][1] - mn0);
                s[nt][2] = ex2(s[nt][2] - mn1);
                s[nt][3] = ex2(s[nt][3] - mn1);
                sum0 += s[nt][0] + s[nt][1];
                sum1 += s[nt][2] + s[nt][3];
            }
#pragma unroll
            for (int off = 1; off < 4; off <<= 1) {
                sum0 += __shfl_xor_sync(0xffffffffu, sum0, off);
                sum1 += __shfl_xor_sync(0xffffffffu, sum1, off);
            }
            l_[0] = l_[0] * sc0 + sum0;
            l_[1] = l_[1] * sc1 + sum1;
            m_[0] = mn0;
            m_[1] = mn1;
#pragma unroll
            for (int dt = 0; dt < 8; dt++) {
                o[dt][0] *= sc0; o[dt][1] *= sc0;
                o[dt][2] *= sc1; o[dt][3] *= sc1;
            }

            // O += P @ V — P straight from S fragments (no smem round-trip)
#pragma unroll
            for (int ch = 0; ch < 4; ch++) {
                unsigned pa[4];
                pa[0] = h2u(__floats2half2_rn(s[2 * ch][0], s[2 * ch][1]));
                pa[1] = h2u(__floats2half2_rn(s[2 * ch][2], s[2 * ch][3]));
                pa[2] = h2u(__floats2half2_rn(s[2 * ch + 1][0], s[2 * ch + 1][1]));
                pa[3] = h2u(__floats2half2_rn(s[2 * ch + 1][2], s[2 * ch + 1][3]));
#pragma unroll
                for (int dtp = 0; dtp < 4; dtp++) {
                    unsigned r[4];
                    ldm_x4t(r, Vtb + 2 * (ch * 16 * VSH + dtp * 16));
                    mma_fp16(o[2 * dtp], pa, r);
                    mma_fp16(o[2 * dtp + 1], pa, r + 2);
                }
            }
        }

        // normalize + store fp16 to g_O (B,T,C)
        float inv0 = 1.f / l_[0];
        float inv1 = 1.f / l_[1];
#pragma unroll
        for (int dt = 0; dt < 8; dt++) {
            int col = h * 64 + dt * 8 + 2 * gc;
            *(__half2*)&g_O[((size_t)b * SEQ + row0) * N_EMBD + col] =
                __floats2half2_rn(o[dt][0] * inv0, o[dt][1] * inv0);
            *(__half2*)&g_O[((size_t)b * SEQ + row1) * N_EMBD + col] =
                __floats2half2_rn(o[dt][2] * inv1, o[dt][3] * inv1);
        }
        __syncthreads();   // smem reuse safety before next pass
    }
}

// ---------------------------------------------------------------------------
extern "C" void kernel_launch(void* const* d_in, const int* in_sizes, int n_in,
                              void* d_out, int out_size)
{
    const float* x  = (const float*)d_in[0];
    const float* Wq = (const float*)d_in[1];
    const float* bq = (const float*)d_in[2];
    const float* Wk = (const float*)d_in[3];
    const float* bk = (const float*)d_in[4];
    const float* Wv = (const float*)d_in[5];
    const float* bv = (const float*)d_in[6];
    const float* Wp = (const float*)d_in[7];
    const float* bp = (const float*)d_in[8];
    float* out = (float*)d_out;

    cudaFuncSetAttribute(qkv_gemm_kernel,
                         cudaFuncAttributeMaxDynamicSharedMemorySize,
                         GEMM_SMEM_BYTES);
    cudaFuncSetAttribute(proj_gemm_kernel,
                         cudaFuncAttributeMaxDynamicSharedMemorySize,
                         GEMM_SMEM_BYTES);
    cudaFuncSetAttribute(attn_kernel,
                         cudaFuncAttributeMaxDynamicSharedMemorySize,
                         ATTN_SMEM_BYTES);

    // fused prep: z 0..3 = W transpose (32x32 grid), z 4..11 = x cast
    prep_kernel<<<dim3(32, 32, 12), dim3(32, 8)>>>(x, Wq, Wk, Wv, Wp);

    qkv_gemm_kernel<<<dim3(4, 64, 3), 256, GEMM_SMEM_BYTES>>>(bq, bk, bv);

    attn_kernel<<<dim3(8, N_HEAD, BATCH), 256, ATTN_SMEM_BYTES>>>();

    proj_gemm_kernel<<<dim3(4, 64, 1), 256, GEMM_SMEM_BYTES>>>(bp, out);
}

// round 15
// speedup vs baseline: 1.1476x; 1.1081x over previous
#include <cuda_runtime.h>
#include <cuda_fp16.h>
#include <math.h>
#include <stdint.h>

#define N_EMBD   1024
#define N_HEAD   16
#define HEAD_DIM 64
#define BATCH    4
#define SEQ      2048
#define M_TOT    8192
#define QSCALE   (0.125f * 1.44269504088896340736f)   // 1/sqrt(64) * log2(e)

// ---------------------------------------------------------------------------
// Device scratch (fp16). Q,K,V all (B,H,T,D); O (B,T,C).
// ---------------------------------------------------------------------------
__device__ __half g_X[(size_t)M_TOT * N_EMBD];
__device__ __half g_Wt[4][(size_t)N_EMBD * N_EMBD];   // W^T [n][k]
__device__ __half g_Q[(size_t)BATCH * N_HEAD * SEQ * HEAD_DIM];
__device__ __half g_K[(size_t)BATCH * N_HEAD * SEQ * HEAD_DIM];
__device__ __half g_V[(size_t)BATCH * N_HEAD * SEQ * HEAD_DIM];
__device__ __half g_O[(size_t)M_TOT * N_EMBD];

// ---------------------------------------------------------------------------
__device__ __forceinline__ void mma_fp16(float* d, const unsigned* a,
                                         const unsigned* b) {
    asm volatile(
        "mma.sync.aligned.m16n8k16.row.col.f32.f16.f16.f32 "
        "{%0,%1,%2,%3}, {%4,%5,%6,%7}, {%8,%9}, {%0,%1,%2,%3};"
        : "+f"(d[0]), "+f"(d[1]), "+f"(d[2]), "+f"(d[3])
        : "r"(a[0]), "r"(a[1]), "r"(a[2]), "r"(a[3]), "r"(b[0]), "r"(b[1]));
}

__device__ __forceinline__ void ldm_x4(unsigned* r, uint32_t a) {
    asm volatile("ldmatrix.sync.aligned.m8n8.x4.shared.b16 {%0,%1,%2,%3}, [%4];"
                 : "=r"(r[0]), "=r"(r[1]), "=r"(r[2]), "=r"(r[3]) : "r"(a));
}
__device__ __forceinline__ void ldm_x4t(unsigned* r, uint32_t a) {
    asm volatile("ldmatrix.sync.aligned.m8n8.x4.trans.shared.b16 {%0,%1,%2,%3}, [%4];"
                 : "=r"(r[0]), "=r"(r[1]), "=r"(r[2]), "=r"(r[3]) : "r"(a));
}

__device__ __forceinline__ void cp16(void* smem_dst, const void* gsrc) {
    unsigned u = (unsigned)__cvta_generic_to_shared(smem_dst);
    asm volatile("cp.async.cg.shared.global [%0], [%1], 16;\n"
                 :: "r"(u), "l"(gsrc));
}
__device__ __forceinline__ void cp16ca(void* smem_dst, const void* gsrc) {
    unsigned u = (unsigned)__cvta_generic_to_shared(smem_dst);
    asm volatile("cp.async.ca.shared.global [%0], [%1], 16;\n"
                 :: "r"(u), "l"(gsrc));
}
#define CP_COMMIT() asm volatile("cp.async.commit_group;\n" ::: "memory")
#define CP_WAIT(N)  asm volatile("cp.async.wait_group %0;\n" :: "n"(N) : "memory")

__device__ __forceinline__ uint32_t smem_u32(const void* p) {
    return (uint32_t)__cvta_generic_to_shared(p);
}
__device__ __forceinline__ unsigned h2u(__half2 h) { return *(unsigned*)&h; }

__device__ __forceinline__ float ex2(float x) {
    float r;
    asm("ex2.approx.f32 %0, %1;" : "=f"(r) : "f"(x));
    return r;
}

// ---------------------------------------------------------------------------
// prep: fused x-cast + W-transpose. z=0..3 -> W q/k/v/p; z=4..11 -> x slabs.
// ---------------------------------------------------------------------------
__global__ void prep_kernel(const float* __restrict__ x,
                            const float* __restrict__ Wq,
                            const float* __restrict__ Wk,
                            const float* __restrict__ Wv,
                            const float* __restrict__ Wp) {
    int z = blockIdx.z;
    if (z >= 4) {
        size_t i = ((size_t)(z - 4) * 1024 + blockIdx.y * 32 + blockIdx.x) * 256 +
                   threadIdx.y * 32 + threadIdx.x;
        if (i < (size_t)M_TOT * N_EMBD / 4) {
            float4 v = ((const float4*)x)[i];
            uint2 u;
            u.x = h2u(__floats2half2_rn(v.x, v.y));
            u.y = h2u(__floats2half2_rn(v.z, v.w));
            ((uint2*)g_X)[i] = u;
        }
        return;
    }
    __shared__ float tile[32][33];
    const float* W = (z == 0) ? Wq : (z == 1) ? Wk : (z == 2) ? Wv : Wp;
    int x0 = blockIdx.x * 32;
    int y0 = blockIdx.y * 32;
    int tx = threadIdx.x;
    for (int i = threadIdx.y; i < 32; i += 8)
        tile[i][tx] = W[(size_t)(y0 + i) * N_EMBD + x0 + tx];
    __syncthreads();
    for (int i = threadIdx.y; i < 32; i += 8)
        g_Wt[z][(size_t)(x0 + i) * N_EMBD + y0 + tx] = __float2half(tile[tx][i]);
}

// ---------------------------------------------------------------------------
// fp16 GEMM (ldmatrix): block 128x128, 8 warps (2x4) of 64x32, BK=32,
// 2-stage cp.async double buffer, .ca loads. acc 64 regs -> ~110 regs/thread,
// __launch_bounds__(256,2) -> 2 CTAs/SM, cross-CTA load/compute overlap.
// smem: 2 stages x (128+128) x 40 halves = 40960 bytes.
// ---------------------------------------------------------------------------
#define GSTR 40
#define A_OFF(buf) ((buf) * 5120)
#define B_OFF(buf) (10240 + (buf) * 5120)
#define GEMM_SMEM_BYTES 40960

__device__ __forceinline__ void gemm_load_stage(
    const __half* __restrict__ A, const __half* __restrict__ Bt,
    int m0, int n0, int kb, __half* smem, int buf, int tid)
{
    const int k0 = kb * 32;
    // A: 128 rows x 4 chunks = 512 cp16 (2 per thread)
#pragma unroll
    for (int i = 0; i < 2; i++) {
        int idx = tid + i * 256;
        int r = idx >> 2, ch = idx & 3;
        cp16ca(smem + A_OFF(buf) + r * GSTR + ch * 8,
               A + (size_t)(m0 + r) * N_EMBD + k0 + ch * 8);
    }
    // B: 128 rows x 4 chunks = 512 cp16 (2 per thread)
#pragma unroll
    for (int i = 0; i < 2; i++) {
        int idx = tid + i * 256;
        int r = idx >> 2, ch = idx & 3;
        cp16ca(smem + B_OFF(buf) + r * GSTR + ch * 8,
               Bt + (size_t)(n0 + r) * N_EMBD + k0 + ch * 8);
    }
}

__device__ __forceinline__ void gemm_fp16_main(
    const __half* __restrict__ A, const __half* __restrict__ Bt,
    int m0, int n0, __half* smem, float acc[4][4][4])
{
    const int tid = threadIdx.x;
    const int warp = tid >> 5, lane = tid & 31;
    const int wm = (warp >> 2) * 64;       // warpM in {0,1}
    const int wn = (warp & 3) * 32;        // warpN in {0..3}
    const uint32_t sb = smem_u32(smem);
    const int a_lane = ((lane & 15) + wm) * GSTR + (lane >> 4) * 8;
    const int b_lane = ((lane >> 4) * 8 + (lane & 7) + wn) * GSTR +
                       ((lane >> 3) & 1) * 8;

#pragma unroll
    for (int mt = 0; mt < 4; mt++)
#pragma unroll
        for (int nt = 0; nt < 4; nt++)
#pragma unroll
            for (int j = 0; j < 4; j++) acc[mt][nt][j] = 0.f;

    gemm_load_stage(A, Bt, m0, n0, 0, smem, 0, tid);
    CP_COMMIT();

    for (int kb = 0; kb < 32; kb++) {
        __syncthreads();
        if (kb + 1 < 32) {
            gemm_load_stage(A, Bt, m0, n0, kb + 1, smem, (kb + 1) & 1, tid);
            CP_COMMIT();
            CP_WAIT(1);
        } else {
            CP_WAIT(0);
        }
        __syncthreads();

        const uint32_t Ab = sb + 2 * (A_OFF(kb & 1) + a_lane);
        const uint32_t Bb = sb + 2 * (B_OFF(kb & 1) + b_lane);
#pragma unroll
        for (int kk = 0; kk < 32; kk += 16) {
            unsigned af[4][4];
#pragma unroll
            for (int mt = 0; mt < 4; mt++)
                ldm_x4(af[mt], Ab + 2 * (mt * 16 * GSTR + kk));
            unsigned bf[4][2];
#pragma unroll
            for (int ntp = 0; ntp < 2; ntp++) {
                unsigned r[4];
                ldm_x4(r, Bb + 2 * (ntp * 16 * GSTR + kk));
                bf[2 * ntp][0] = r[0]; bf[2 * ntp][1] = r[1];
                bf[2 * ntp + 1][0] = r[2]; bf[2 * ntp + 1][1] = r[3];
            }
#pragma unroll
            for (int mt = 0; mt < 4; mt++)
#pragma unroll
                for (int nt = 0; nt < 4; nt++)
                    mma_fp16(acc[mt][nt], af[mt], bf[nt]);
        }
    }
}

// QKV: out (B,H,T,D) fp16, +bias; Q pre-scaled by 1/8*log2(e).
__global__ __launch_bounds__(256, 2) void qkv_gemm_kernel(
    const float* __restrict__ bq, const float* __restrict__ bk,
    const float* __restrict__ bv)
{
    extern __shared__ __half smem[];
    const int z = blockIdx.z;
    const float* bias = (z == 0) ? bq : (z == 1) ? bk : bv;
    __half* out = (z == 0) ? g_Q : (z == 1) ? g_K : g_V;
    const float oscale = (z == 0) ? QSCALE : 1.0f;
    const int m0 = blockIdx.y * 128, n0 = blockIdx.x * 128;

    float acc[4][4][4];
    gemm_fp16_main(g_X, g_Wt[z], m0, n0, smem, acc);

    const int tid = threadIdx.x;
    const int warp = tid >> 5, lane = tid & 31;
    const int wm = (warp >> 2) * 64, wn = (warp & 3) * 32;
    const int gr = lane >> 2, gc = lane & 3;

#pragma unroll
    for (int mt = 0; mt < 4; mt++) {
#pragma unroll
        for (int nt = 0; nt < 4; nt++) {
            int n = n0 + wn + nt * 8 + 2 * gc;
            int h = n >> 6, d = n & 63;
            float2 bi = *(const float2*)&bias[n];
#pragma unroll
            for (int half_ = 0; half_ < 2; half_++) {
                int m = m0 + wm + mt * 16 + gr + half_ * 8;
                int bb = m >> 11, t = m & (SEQ - 1);
                float c0 = (acc[mt][nt][half_ * 2 + 0] + bi.x) * oscale;
                float c1 = (acc[mt][nt][half_ * 2 + 1] + bi.y) * oscale;
                *(__half2*)&out[(((size_t)(bb * N_HEAD + h)) * SEQ + t) * 64 + d] =
                    __floats2half2_rn(c0, c1);
            }
        }
    }
}

__global__ __launch_bounds__(256, 2) void proj_gemm_kernel(
    const float* __restrict__ bp, float* __restrict__ out)
{
    extern __shared__ __half smem[];
    const int m0 = blockIdx.y * 128, n0 = blockIdx.x * 128;

    float acc[4][4][4];
    gemm_fp16_main(g_O, g_Wt[3], m0, n0, smem, acc);

    const int tid = threadIdx.x;
    const int warp = tid >> 5, lane = tid & 31;
    const int wm = (warp >> 2) * 64, wn = (warp & 3) * 32;
    const int gr = lane >> 2, gc = lane & 3;

#pragma unroll
    for (int mt = 0; mt < 4; mt++) {
#pragma unroll
        for (int nt = 0; nt < 4; nt++) {
            int n = n0 + wn + nt * 8 + 2 * gc;
            float2 bi = *(const float2*)&bp[n];
#pragma unroll
            for (int half_ = 0; half_ < 2; half_++) {
                int m = m0 + wm + mt * 16 + gr + half_ * 8;
                float2 v = make_float2(acc[mt][nt][half_ * 2 + 0] + bi.x,
                                       acc[mt][nt][half_ * 2 + 1] + bi.y);
                *(float2*)&out[(size_t)m * N_EMBD + n] = v;
            }
        }
    }
}

// ---------------------------------------------------------------------------
// Fused causal attention (UNCHANGED, 147.4 us): fp16 mma, 64-key tiles,
// cp.async double-buffered, paired q-tiles, Q + P in registers, V natural
// layout via ldmatrix.trans, ex2 softmax in log2 domain.
// ---------------------------------------------------------------------------
#define QSH 72
#define KSH 72
#define VSH 72
#define QS_H (128 * QSH)
#define KS_H (64 * KSH)
#define VS_H (64 * VSH)
#define ATTN_SMEM_BYTES ((QS_H + 2 * KS_H + 2 * VS_H) * 2)  // 55296

__global__ __launch_bounds__(256, 2) void attn_kernel()
{
    extern __shared__ __half sm[];
    __half* Qs  = sm;
    __half* Ks0 = Qs + QS_H;
    __half* Vs0 = Ks0 + 2 * KS_H;
    const uint32_t sb = smem_u32(sm);

    const int px = blockIdx.x;          // 0..7
    const int h  = blockIdx.y;
    const int b  = blockIdx.z;
    const int tid  = threadIdx.x;
    const int warp = tid >> 5, lane = tid & 31;
    const int gr = lane >> 2, gc = lane & 3;
    const int rw = warp * 16;

    const __half* Kb = g_K + ((size_t)(b * N_HEAD + h)) * SEQ * 64;
    const __half* Vb = g_V + ((size_t)(b * N_HEAD + h)) * SEQ * 64;

    const int q_lane = (rw + (lane & 15)) * QSH + (lane >> 4) * 8;
    const int k_lane = ((lane >> 4) * 8 + (lane & 7)) * KSH + ((lane >> 3) & 1) * 8;
    const int v_lane = (lane & 15) * VSH + (lane >> 4) * 8;

    for (int pass = 0; pass < 2; pass++) {
        const int qt = pass ? px : (15 - px);
        const int q0 = qt * 128;
        const int nkt = 2 * qt + 2;     // 64-key tiles

        const __half* Qg = g_Q + (((size_t)(b * N_HEAD + h)) * SEQ + q0) * 64;

        // prologue: Q tile + KV tile 0 in one cp.async group
        {
#pragma unroll
            for (int i = 0; i < 4; i++) {
                int idx = tid + i * 256;
                int r = idx >> 3, ch = idx & 7;
                cp16(&Qs[r * QSH + ch * 8], Qg + r * 64 + ch * 8);
            }
#pragma unroll
            for (int i = 0; i < 2; i++) {
                int idx = tid + i * 256;
                int r = idx >> 3, ch = idx & 7;
                cp16(&Ks0[r * KSH + ch * 8], Kb + r * 64 + ch * 8);
                cp16(&Vs0[r * VSH + ch * 8], Vb + r * 64 + ch * 8);
            }
            CP_COMMIT();
        }

        float m_[2] = {-1e30f, -1e30f};
        float l_[2] = {0.f, 0.f};
        float o[8][4];
#pragma unroll
        for (int dt = 0; dt < 8; dt++)
#pragma unroll
            for (int j = 0; j < 4; j++) o[dt][j] = 0.f;

        unsigned qf[4][4];              // Q fragments, loaded once per pass
        const int row0 = q0 + rw + gr;
        const int row1 = row0 + 8;

        for (int kb = 0; kb < nkt; kb++) {
            __syncthreads();
            if (kb + 1 < nkt) {
                const __half* Kg = Kb + (size_t)(kb + 1) * 64 * 64;
                const __half* Vg = Vb + (size_t)(kb + 1) * 64 * 64;
                __half* Kd = Ks0 + ((kb + 1) & 1) * KS_H;
                __half* Vd = Vs0 + ((kb + 1) & 1) * VS_H;
#pragma unroll
                for (int i = 0; i < 2; i++) {
                    int idx = tid + i * 256;
                    int r = idx >> 3, ch = idx & 7;
                    cp16(&Kd[r * KSH + ch * 8], Kg + r * 64 + ch * 8);
                    cp16(&Vd[r * VSH + ch * 8], Vg + r * 64 + ch * 8);
                }
                CP_COMMIT();
                CP_WAIT(1);
            } else {
                CP_WAIT(0);
            }
            __syncthreads();

            if (kb == 0) {
                const uint32_t Qsb = sb + 2 * q_lane;
#pragma unroll
                for (int ch = 0; ch < 4; ch++)
                    ldm_x4(qf[ch], Qsb + 2 * (ch * 16));
            }

            if (kb * 64 > q0 + rw + 15) continue;   // fully masked for warp

            const uint32_t Ktb = sb + 2 * (QS_H + (kb & 1) * KS_H + k_lane);
            const uint32_t Vtb = sb + 2 * (QS_H + 2 * KS_H + (kb & 1) * VS_H + v_lane);

            // S = Q K^T (16 x 64) — S already in log2 domain (Q prescaled)
            float s[8][4];
#pragma unroll
            for (int nt = 0; nt < 8; nt++)
#pragma unroll
                for (int j = 0; j < 4; j++) s[nt][j] = 0.f;

#pragma unroll
            for (int ch = 0; ch < 4; ch++) {
                int k = ch * 16;
#pragma unroll
                for (int ntp = 0; ntp < 4; ntp++) {
                    unsigned r[4];
                    ldm_x4(r, Ktb + 2 * (ntp * 16 * KSH + k));
                    mma_fp16(s[2 * ntp], qf[ch], r);
                    mma_fp16(s[2 * ntp + 1], qf[ch], r + 2);
                }
            }

            // causal mask (only diagonal-straddling tiles)
            if (kb * 64 + 63 > q0 + rw) {
#pragma unroll
                for (int nt = 0; nt < 8; nt++) {
                    int c0 = kb * 64 + nt * 8 + 2 * gc;
                    if (c0     > row0) s[nt][0] = -1e30f;
                    if (c0 + 1 > row0) s[nt][1] = -1e30f;
                    if (c0     > row1) s[nt][2] = -1e30f;
                    if (c0 + 1 > row1) s[nt][3] = -1e30f;
                }
            }

            // online softmax in log2 domain: P = 2^(S - m)
            float mx0 = -1e30f, mx1 = -1e30f;
#pragma unroll
            for (int nt = 0; nt < 8; nt++) {
                mx0 = fmaxf(mx0, fmaxf(s[nt][0], s[nt][1]));
                mx1 = fmaxf(mx1, fmaxf(s[nt][2], s[nt][3]));
            }
#pragma unroll
            for (int off = 1; off < 4; off <<= 1) {
                mx0 = fmaxf(mx0, __shfl_xor_sync(0xffffffffu, mx0, off));
                mx1 = fmaxf(mx1, __shfl_xor_sync(0xffffffffu, mx1, off));
            }
            float mn0 = fmaxf(m_[0], mx0), mn1 = fmaxf(m_[1], mx1);
            float sc0 = ex2(m_[0] - mn0), sc1 = ex2(m_[1] - mn1);
            float sum0 = 0.f, sum1 = 0.f;
#pragma unroll
            for (int nt = 0; nt < 8; nt++) {
                s[nt][0] = ex2(s[nt][0] - mn0);
                s[nt][1] = ex2(s[nt][1] - mn0);
                s[nt][2] = ex2(s[nt][2] - mn1);
                s[nt][3] = ex2(s[nt][3] - mn1);
                sum0 += s[nt][0] + s[nt][1];
                sum1 += s[nt][2] + s[nt][3];
            }
#pragma unroll
            for (int off = 1; off < 4; off <<= 1) {
                sum0 += __shfl_xor_sync(0xffffffffu, sum0, off);
                sum1 += __shfl_xor_sync(0xffffffffu, sum1, off);
            }
            l_[0] = l_[0] * sc0 + sum0;
            l_[1] = l_[1] * sc1 + sum1;
            m_[0] = mn0;
            m_[1] = mn1;
#pragma unroll
            for (int dt = 0; dt < 8; dt++) {
                o[dt][0] *= sc0; o[dt][1] *= sc0;
                o[dt][2] *= sc1; o[dt][3] *= sc1;
            }

            // O += P @ V — P straight from S fragments (no smem round-trip)
#pragma unroll
            for (int ch = 0; ch < 4; ch++) {
                unsigned pa[4];
                pa[0] = h2u(__floats2half2_rn(s[2 * ch][0], s[2 * ch][1]));
                pa[1] = h2u(__floats2half2_rn(s[2 * ch][2], s[2 * ch][3]));
                pa[2] = h2u(__floats2half2_rn(s[2 * ch + 1][0], s[2 * ch + 1][1]));
                pa[3] = h2u(__floats2half2_rn(s[2 * ch + 1][2], s[2 * ch + 1][3]));
#pragma unroll
                for (int dtp = 0; dtp < 4; dtp++) {
                    unsigned r[4];
                    ldm_x4t(r, Vtb + 2 * (ch * 16 * VSH + dtp * 16));
                    mma_fp16(o[2 * dtp], pa, r);
                    mma_fp16(o[2 * dtp + 1], pa, r + 2);
                }
            }
        }

        // normalize + store fp16 to g_O (B,T,C)
        float inv0 = 1.f / l_[0];
        float inv1 = 1.f / l_[1];
#pragma unroll
        for (int dt = 0; dt < 8; dt++) {
            int col = h * 64 + dt * 8 + 2 * gc;
            *(__half2*)&g_O[((size_t)b * SEQ + row0) * N_EMBD + col] =
                __floats2half2_rn(o[dt][0] * inv0, o[dt][1] * inv0);
            *(__half2*)&g_O[((size_t)b * SEQ + row1) * N_EMBD + col] =
                __floats2half2_rn(o[dt][2] * inv1, o[dt][3] * inv1);
        }
        __syncthreads();   // smem reuse safety before next pass
    }
}

// ---------------------------------------------------------------------------
extern "C" void kernel_launch(void* const* d_in, const int* in_sizes, int n_in,
                              void* d_out, int out_size)
{
    const float* x  = (const float*)d_in[0];
    const float* Wq = (const float*)d_in[1];
    const float* bq = (const float*)d_in[2];
    const float* Wk = (const float*)d_in[3];
    const float* bk = (const float*)d_in[4];
    const float* Wv = (const float*)d_in[5];
    const float* bv = (const float*)d_in[6];
    const float* Wp = (const float*)d_in[7];
    const float* bp = (const float*)d_in[8];
    float* out = (float*)d_out;

    cudaFuncSetAttribute(qkv_gemm_kernel,
                         cudaFuncAttributeMaxDynamicSharedMemorySize,
                         GEMM_SMEM_BYTES);
    cudaFuncSetAttribute(proj_gemm_kernel,
                         cudaFuncAttributeMaxDynamicSharedMemorySize,
                         GEMM_SMEM_BYTES);
    cudaFuncSetAttribute(attn_kernel,
                         cudaFuncAttributeMaxDynamicSharedMemorySize,
                         ATTN_SMEM_BYTES);

    // fused prep: z 0..3 = W transpose, z 4..11 = x cast
    prep_kernel<<<dim3(32, 32, 12), dim3(32, 8)>>>(x, Wq, Wk, Wv, Wp);

    qkv_gemm_kernel<<<dim3(8, 64, 3), 256, GEMM_SMEM_BYTES>>>(bq, bk, bv);

    attn_kernel<<<dim3(8, N_HEAD, BATCH), 256, ATTN_SMEM_BYTES>>>();

    proj_gemm_kernel<<<dim3(8, 64, 1), 256, GEMM_SMEM_BYTES>>>(bp, out);
}